// round 1
// baseline (speedup 1.0000x reference)
#include <cuda_runtime.h>

#define DIMX 32
#define NB   6
#define BB   16
#define NN   256
#define XPD  16
#define TPD  8

typedef unsigned long long u64;

// Per-batch precomputed conditioning constants:
//  g_cf[b][k][d] = f_bh[k][d] + f_bz[k][d] + sum_m et[b][m] * f_Wz[k][2+m][d]
//  g_cg[b][k][d] = g_bh[k][d] + g_bz[k][d] + sum_m ex[b][m] * g_Wz[k][32+m][d]
__device__ float g_cf[BB * NB * DIMX];
__device__ float g_cg[BB * NB * DIMX];

// ---------------- packed f32x2 helpers (sm_100+) ----------------
__device__ __forceinline__ u64 ffma2(u64 a, u64 b, u64 c) {
    u64 d;
    asm("fma.rn.f32x2 %0, %1, %2, %3;" : "=l"(d) : "l"(a), "l"(b), "l"(c));
    return d;
}
__device__ __forceinline__ u64 pack2(float v) {
    u64 r;
    asm("mov.b64 %0, {%1, %1};" : "=l"(r) : "f"(v));
    return r;
}
__device__ __forceinline__ float2 unpack2(u64 v) {
    float lo, hi;
    asm("mov.b64 {%0, %1}, %2;" : "=f"(lo), "=f"(hi) : "l"(v));
    return make_float2(lo, hi);
}

// ---------------- precompute: ex/et embeddings + folded constants ----------------
__global__ void precompute_kernel(
    const float* __restrict__ x_params,   // [B,16]
    const float* __restrict__ t_params,   // [B,8]
    const float* __restrict__ xW1, const float* __restrict__ xb1,
    const float* __restrict__ xW2, const float* __restrict__ xb2,
    const float* __restrict__ tW1, const float* __restrict__ tb1,
    const float* __restrict__ tW2, const float* __restrict__ tb2,
    const float* __restrict__ f_bh, const float* __restrict__ f_Wz, const float* __restrict__ f_bz,
    const float* __restrict__ g_bh, const float* __restrict__ g_Wz, const float* __restrict__ g_bz)
{
    int b = blockIdx.x;
    int d = threadIdx.x;  // 0..31
    __shared__ float hid[DIMX], ex_s[DIMX], et_s[DIMX];

    // ex = sin(xp @ xW1 + xb1) @ xW2 + xb2
    float a = xb1[d];
    #pragma unroll
    for (int m = 0; m < XPD; m++) a += x_params[b * XPD + m] * xW1[m * DIMX + d];
    hid[d] = sinf(a);
    __syncthreads();
    float e = xb2[d];
    #pragma unroll
    for (int m = 0; m < DIMX; m++) e += hid[m] * xW2[m * DIMX + d];
    ex_s[d] = e;
    __syncthreads();

    // et = sin(tp @ tW1 + tb1) @ tW2 + tb2
    a = tb1[d];
    #pragma unroll
    for (int m = 0; m < TPD; m++) a += t_params[b * TPD + m] * tW1[m * DIMX + d];
    hid[d] = sinf(a);
    __syncthreads();
    e = tb2[d];
    #pragma unroll
    for (int m = 0; m < DIMX; m++) e += hid[m] * tW2[m * DIMX + d];
    et_s[d] = e;
    __syncthreads();

    for (int k = 0; k < NB; k++) {
        float cf = f_bh[k * DIMX + d] + f_bz[k * DIMX + d];
        const float* Wz = f_Wz + k * 34 * DIMX;
        #pragma unroll
        for (int m = 0; m < DIMX; m++) cf += et_s[m] * Wz[(2 + m) * DIMX + d];
        g_cf[(b * NB + k) * DIMX + d] = cf;

        float cg = g_bh[k * DIMX + d] + g_bz[k * DIMX + d];
        const float* gWz = g_Wz + k * 64 * DIMX;
        #pragma unroll
        for (int m = 0; m < DIMX; m++) cg += ex_s[m] * gWz[(32 + m) * DIMX + d];
        g_cg[(b * NB + k) * DIMX + d] = cg;
    }
}

// ---------------- main kernel: one thread per (b,i,j) pair ----------------
// shared layout (floats):
//  s_fWh 6144 | s_gWh 6144 | s_gWz 6144 | s_wzx 192 | s_wzt 192 |
//  s_cf 192 | s_cg 192 | s_h0 32 | s_gh0 32 | s_dW 32  => 19296 floats = 77184 B
#define SMEM_FLOATS 19296
#define SMEM_BYTES  (SMEM_FLOATS * 4)

extern __shared__ float smem[];

__global__ void __launch_bounds__(256, 2) pde_kernel(
    const float* __restrict__ coords,  // [B,N,2]
    const float* __restrict__ f_Wh,    // [6,32,32]
    const float* __restrict__ f_Wz,    // [6,34,32]
    const float* __restrict__ g_Wh,    // [6,32,32]
    const float* __restrict__ g_Wz,    // [6,64,32]
    const float* __restrict__ h0,      // [1,32]
    const float* __restrict__ gh0,     // [1,32]
    const float* __restrict__ dW,      // [32,1]
    const float* __restrict__ dB,      // [1]
    float* __restrict__ out)           // [B,N,N,1]
{
    float* s_fWh = smem;
    float* s_gWh = smem + 6144;
    float* s_gWz = smem + 12288;
    float* s_wzx = smem + 18432;
    float* s_wzt = smem + 18624;
    float* s_cf  = smem + 18816;
    float* s_cg  = smem + 19008;
    float* s_h0  = smem + 19200;
    float* s_gh0 = smem + 19232;
    float* s_dW  = smem + 19264;

    const int tid = threadIdx.x;
    const int p   = blockIdx.x * 256 + tid;
    const int b   = p >> 16;          // N*N = 65536
    const int rem = p & 65535;
    const int i   = rem >> 8;
    const int j   = rem & 255;

    // ---- cooperative weight staging ----
    {
        float4*       dst = (float4*)s_fWh;
        const float4* src = (const float4*)f_Wh;
        for (int q = tid; q < 1536; q += 256) dst[q] = src[q];
        dst = (float4*)s_gWh; src = (const float4*)g_Wh;
        for (int q = tid; q < 1536; q += 256) dst[q] = src[q];
        // g_Wz rows 0..31 of each block (first 1024 floats of each 2048-float chunk)
        for (int q = tid; q < 1536; q += 256) {
            int k = q >> 8;   // 256 float4 per block
            int r = q & 255;
            ((float4*)s_gWz)[q] = ((const float4*)(g_Wz + k * 64 * DIMX))[r];
        }
        if (tid < 192) {
            int k = tid >> 5, d = tid & 31;
            s_wzx[tid] = f_Wz[k * 34 * DIMX + d];
            s_wzt[tid] = f_Wz[k * 34 * DIMX + DIMX + d];
            s_cf[tid]  = g_cf[b * (NB * DIMX) + tid];
            s_cg[tid]  = g_cg[b * (NB * DIMX) + tid];
        }
        if (tid < 32) {
            s_h0[tid]  = h0[tid];
            s_gh0[tid] = gh0[tid];
            s_dW[tid]  = dW[tid];
        }
    }
    __syncthreads();

    const float x = coords[(b * NN + j) * 2 + 0];
    const float t = coords[(b * NN + i) * 2 + 1];
    const u64 xx = pack2(x);
    const u64 tt = pack2(t);

    float h[DIMX];
    #pragma unroll
    for (int d = 0; d < DIMX; d++) h[d] = s_h0[d];

    // ---- f-scan: h = sin(h@Wh + x*wzx + t*wzt + cf) ----
    #pragma unroll 1
    for (int k = 0; k < NB; k++) {
        u64 acc[16];
        const ulonglong2* cfv = (const ulonglong2*)(s_cf  + k * DIMX);
        const ulonglong2* wxv = (const ulonglong2*)(s_wzx + k * DIMX);
        const ulonglong2* wtv = (const ulonglong2*)(s_wzt + k * DIMX);
        #pragma unroll
        for (int q = 0; q < 8; q++) {
            ulonglong2 c = cfv[q], wx = wxv[q], wt = wtv[q];
            acc[2 * q]     = ffma2(xx, wx.x, c.x);
            acc[2 * q + 1] = ffma2(xx, wx.y, c.y);
            acc[2 * q]     = ffma2(tt, wt.x, acc[2 * q]);
            acc[2 * q + 1] = ffma2(tt, wt.y, acc[2 * q + 1]);
        }
        const ulonglong2* Wv = (const ulonglong2*)(s_fWh + k * 1024);
        #pragma unroll
        for (int kk = 0; kk < DIMX; kk++) {
            u64 hv = pack2(h[kk]);
            #pragma unroll
            for (int q = 0; q < 8; q++) {
                ulonglong2 w = Wv[kk * 8 + q];
                acc[2 * q]     = ffma2(hv, w.x, acc[2 * q]);
                acc[2 * q + 1] = ffma2(hv, w.y, acc[2 * q + 1]);
            }
        }
        #pragma unroll
        for (int q = 0; q < 16; q++) {
            float2 v = unpack2(acc[q]);
            h[2 * q]     = __sinf(v.x);
            h[2 * q + 1] = __sinf(v.y);
        }
    }

    // ---- g-scan: gh = sin(gh@gWh + h@gWz[:32] + cg) ----
    float gh[DIMX];
    #pragma unroll
    for (int d = 0; d < DIMX; d++) gh[d] = s_gh0[d];

    #pragma unroll 1
    for (int k = 0; k < NB; k++) {
        u64 acc[16];
        const ulonglong2* cgv = (const ulonglong2*)(s_cg + k * DIMX);
        #pragma unroll
        for (int q = 0; q < 8; q++) {
            ulonglong2 c = cgv[q];
            acc[2 * q] = c.x;
            acc[2 * q + 1] = c.y;
        }
        const ulonglong2* Whv = (const ulonglong2*)(s_gWh + k * 1024);
        const ulonglong2* Wzv = (const ulonglong2*)(s_gWz + k * 1024);
        #pragma unroll
        for (int kk = 0; kk < DIMX; kk++) {
            u64 gv = pack2(gh[kk]);
            u64 hv = pack2(h[kk]);
            #pragma unroll
            for (int q = 0; q < 8; q++) {
                ulonglong2 wh = Whv[kk * 8 + q];
                ulonglong2 wz = Wzv[kk * 8 + q];
                acc[2 * q]     = ffma2(gv, wh.x, acc[2 * q]);
                acc[2 * q + 1] = ffma2(gv, wh.y, acc[2 * q + 1]);
                acc[2 * q]     = ffma2(hv, wz.x, acc[2 * q]);
                acc[2 * q + 1] = ffma2(hv, wz.y, acc[2 * q + 1]);
            }
        }
        #pragma unroll
        for (int q = 0; q < 16; q++) {
            float2 v = unpack2(acc[q]);
            gh[2 * q]     = __sinf(v.x);
            gh[2 * q + 1] = __sinf(v.y);
        }
    }

    // ---- decode ----
    float u = dB[0];
    #pragma unroll
    for (int d = 0; d < DIMX; d++) u = fmaf(gh[d], s_dW[d], u);
    out[p] = u;
}

extern "C" void kernel_launch(void* const* d_in, const int* in_sizes, int n_in,
                              void* d_out, int out_size) {
    const float* coords   = (const float*)d_in[0];
    const float* x_params = (const float*)d_in[1];
    const float* t_params = (const float*)d_in[2];
    const float* xW1 = (const float*)d_in[3];
    const float* xb1 = (const float*)d_in[4];
    const float* xW2 = (const float*)d_in[5];
    const float* xb2 = (const float*)d_in[6];
    const float* tW1 = (const float*)d_in[7];
    const float* tb1 = (const float*)d_in[8];
    const float* tW2 = (const float*)d_in[9];
    const float* tb2 = (const float*)d_in[10];
    const float* h0  = (const float*)d_in[11];
    const float* gh0 = (const float*)d_in[12];
    const float* f_Wh = (const float*)d_in[13];
    const float* f_bh = (const float*)d_in[14];
    const float* f_Wz = (const float*)d_in[15];
    const float* f_bz = (const float*)d_in[16];
    const float* g_Wh = (const float*)d_in[17];
    const float* g_bh = (const float*)d_in[18];
    const float* g_Wz = (const float*)d_in[19];
    const float* g_bz = (const float*)d_in[20];
    const float* dW   = (const float*)d_in[21];
    const float* dB   = (const float*)d_in[22];

    precompute_kernel<<<BB, 32>>>(x_params, t_params, xW1, xb1, xW2, xb2,
                                  tW1, tb1, tW2, tb2,
                                  f_bh, f_Wz, f_bz, g_bh, g_Wz, g_bz);

    cudaFuncSetAttribute(pde_kernel, cudaFuncAttributeMaxDynamicSharedMemorySize, SMEM_BYTES);

    const int total  = BB * NN * NN;         // 1,048,576 pairs
    const int blocks = total / 256;          // 4096
    pde_kernel<<<blocks, 256, SMEM_BYTES>>>(coords, f_Wh, f_Wz, g_Wh, g_Wz,
                                            h0, gh0, dW, dB, (float*)d_out);
}

// round 2
// speedup vs baseline: 1.3747x; 1.3747x over previous
#include <cuda_runtime.h>

#define DIMX 32
#define NB   6
#define BB   16
#define NN   256
#define XPD  16
#define TPD  8

typedef unsigned long long u64;

__device__ float g_cf[BB * NB * DIMX];
__device__ float g_cg[BB * NB * DIMX];

// ---------------- packed f32x2 helpers (sm_100+) ----------------
__device__ __forceinline__ u64 ffma2(u64 a, u64 b, u64 c) {
    u64 d;
    asm("fma.rn.f32x2 %0, %1, %2, %3;" : "=l"(d) : "l"(a), "l"(b), "l"(c));
    return d;
}
__device__ __forceinline__ u64 pack2(float v) {
    u64 r;
    asm("mov.b64 %0, {%1, %1};" : "=l"(r) : "f"(v));
    return r;
}
__device__ __forceinline__ float2 unpack2(u64 v) {
    float lo, hi;
    asm("mov.b64 {%0, %1}, %2;" : "=f"(lo), "=f"(hi) : "l"(v));
    return make_float2(lo, hi);
}

// ---------------- precompute: ex/et embeddings + folded constants ----------------
__global__ void precompute_kernel(
    const float* __restrict__ x_params, const float* __restrict__ t_params,
    const float* __restrict__ xW1, const float* __restrict__ xb1,
    const float* __restrict__ xW2, const float* __restrict__ xb2,
    const float* __restrict__ tW1, const float* __restrict__ tb1,
    const float* __restrict__ tW2, const float* __restrict__ tb2,
    const float* __restrict__ f_bh, const float* __restrict__ f_Wz, const float* __restrict__ f_bz,
    const float* __restrict__ g_bh, const float* __restrict__ g_Wz, const float* __restrict__ g_bz)
{
    int b = blockIdx.x;
    int d = threadIdx.x;  // 0..31
    __shared__ float hid[DIMX], ex_s[DIMX], et_s[DIMX];

    float a = xb1[d];
    #pragma unroll
    for (int m = 0; m < XPD; m++) a += x_params[b * XPD + m] * xW1[m * DIMX + d];
    hid[d] = sinf(a);
    __syncthreads();
    float e = xb2[d];
    #pragma unroll
    for (int m = 0; m < DIMX; m++) e += hid[m] * xW2[m * DIMX + d];
    ex_s[d] = e;
    __syncthreads();

    a = tb1[d];
    #pragma unroll
    for (int m = 0; m < TPD; m++) a += t_params[b * TPD + m] * tW1[m * DIMX + d];
    hid[d] = sinf(a);
    __syncthreads();
    e = tb2[d];
    #pragma unroll
    for (int m = 0; m < DIMX; m++) e += hid[m] * tW2[m * DIMX + d];
    et_s[d] = e;
    __syncthreads();

    for (int k = 0; k < NB; k++) {
        float cf = f_bh[k * DIMX + d] + f_bz[k * DIMX + d];
        const float* Wz = f_Wz + k * 34 * DIMX;
        #pragma unroll
        for (int m = 0; m < DIMX; m++) cf += et_s[m] * Wz[(2 + m) * DIMX + d];
        g_cf[(b * NB + k) * DIMX + d] = cf;

        float cg = g_bh[k * DIMX + d] + g_bz[k * DIMX + d];
        const float* gWz = g_Wz + k * 64 * DIMX;
        #pragma unroll
        for (int m = 0; m < DIMX; m++) cg += ex_s[m] * gWz[(32 + m) * DIMX + d];
        g_cg[(b * NB + k) * DIMX + d] = cg;
    }
}

// ---------------- main kernel: TWO pairs per thread, shared weight loads ----------------
#define SMEM_FLOATS 19296
#define SMEM_BYTES  (SMEM_FLOATS * 4)

extern __shared__ float smem[];

__global__ void __launch_bounds__(256, 1) pde_kernel(
    const float* __restrict__ coords,
    const float* __restrict__ f_Wh,
    const float* __restrict__ f_Wz,
    const float* __restrict__ g_Wh,
    const float* __restrict__ g_Wz,
    const float* __restrict__ h0,
    const float* __restrict__ gh0,
    const float* __restrict__ dW,
    const float* __restrict__ dB,
    float* __restrict__ out)
{
    float* s_fWh = smem;
    float* s_gWh = smem + 6144;
    float* s_gWz = smem + 12288;
    float* s_wzx = smem + 18432;
    float* s_wzt = smem + 18624;
    float* s_cf  = smem + 18816;
    float* s_cg  = smem + 19008;
    float* s_h0  = smem + 19200;
    float* s_gh0 = smem + 19232;
    float* s_dW  = smem + 19264;

    const int tid = threadIdx.x;
    // block covers 2 rows of one batch: 128 threads per row, 2 j's per thread
    const int b  = blockIdx.x >> 7;                  // 128 blocks per batch
    const int i  = ((blockIdx.x & 127) << 1) + (tid >> 7);
    const int j0 = tid & 127;
    const int j1 = j0 + 128;

    // ---- cooperative weight staging ----
    {
        float4*       dst = (float4*)s_fWh;
        const float4* src = (const float4*)f_Wh;
        for (int q = tid; q < 1536; q += 256) dst[q] = src[q];
        dst = (float4*)s_gWh; src = (const float4*)g_Wh;
        for (int q = tid; q < 1536; q += 256) dst[q] = src[q];
        for (int q = tid; q < 1536; q += 256) {
            int k = q >> 8;
            int r = q & 255;
            ((float4*)s_gWz)[q] = ((const float4*)(g_Wz + k * 64 * DIMX))[r];
        }
        if (tid < 192) {
            int k = tid >> 5, d = tid & 31;
            s_wzx[tid] = f_Wz[k * 34 * DIMX + d];
            s_wzt[tid] = f_Wz[k * 34 * DIMX + DIMX + d];
            s_cf[tid]  = g_cf[b * (NB * DIMX) + tid];
            s_cg[tid]  = g_cg[b * (NB * DIMX) + tid];
        }
        if (tid < 32) {
            s_h0[tid]  = h0[tid];
            s_gh0[tid] = gh0[tid];
            s_dW[tid]  = dW[tid];
        }
    }
    __syncthreads();

    const float x0 = coords[(b * NN + j0) * 2 + 0];
    const float x1 = coords[(b * NN + j1) * 2 + 0];
    const float t  = coords[(b * NN + i) * 2 + 1];
    const u64 xx0 = pack2(x0);
    const u64 xx1 = pack2(x1);
    const u64 tt  = pack2(t);

    float hA[DIMX], hB[DIMX];
    #pragma unroll
    for (int d = 0; d < DIMX; d++) { hA[d] = s_h0[d]; hB[d] = s_h0[d]; }

    // ---- f-scan ----
    #pragma unroll 1
    for (int k = 0; k < NB; k++) {
        u64 accA[16], accB[16];
        const ulonglong2* cfv = (const ulonglong2*)(s_cf  + k * DIMX);
        const ulonglong2* wxv = (const ulonglong2*)(s_wzx + k * DIMX);
        const ulonglong2* wtv = (const ulonglong2*)(s_wzt + k * DIMX);
        #pragma unroll
        for (int q = 0; q < 8; q++) {
            ulonglong2 c = cfv[q], wx = wxv[q], wt = wtv[q];
            u64 base0 = ffma2(tt, wt.x, c.x);
            u64 base1 = ffma2(tt, wt.y, c.y);
            accA[2 * q]     = ffma2(xx0, wx.x, base0);
            accA[2 * q + 1] = ffma2(xx0, wx.y, base1);
            accB[2 * q]     = ffma2(xx1, wx.x, base0);
            accB[2 * q + 1] = ffma2(xx1, wx.y, base1);
        }
        const ulonglong2* Wv = (const ulonglong2*)(s_fWh + k * 1024);
        #pragma unroll
        for (int kk = 0; kk < DIMX; kk++) {
            u64 hvA = pack2(hA[kk]);
            u64 hvB = pack2(hB[kk]);
            #pragma unroll
            for (int q = 0; q < 8; q++) {
                ulonglong2 w = Wv[kk * 8 + q];
                accA[2 * q]     = ffma2(hvA, w.x, accA[2 * q]);
                accA[2 * q + 1] = ffma2(hvA, w.y, accA[2 * q + 1]);
                accB[2 * q]     = ffma2(hvB, w.x, accB[2 * q]);
                accB[2 * q + 1] = ffma2(hvB, w.y, accB[2 * q + 1]);
            }
        }
        #pragma unroll
        for (int q = 0; q < 16; q++) {
            float2 vA = unpack2(accA[q]);
            float2 vB = unpack2(accB[q]);
            hA[2 * q]     = __sinf(vA.x);
            hA[2 * q + 1] = __sinf(vA.y);
            hB[2 * q]     = __sinf(vB.x);
            hB[2 * q + 1] = __sinf(vB.y);
        }
    }

    // ---- g-scan ----
    float ghA[DIMX], ghB[DIMX];
    #pragma unroll
    for (int d = 0; d < DIMX; d++) { ghA[d] = s_gh0[d]; ghB[d] = s_gh0[d]; }

    #pragma unroll 1
    for (int k = 0; k < NB; k++) {
        u64 accA[16], accB[16];
        const ulonglong2* cgv = (const ulonglong2*)(s_cg + k * DIMX);
        #pragma unroll
        for (int q = 0; q < 8; q++) {
            ulonglong2 c = cgv[q];
            accA[2 * q] = c.x;  accA[2 * q + 1] = c.y;
            accB[2 * q] = c.x;  accB[2 * q + 1] = c.y;
        }
        const ulonglong2* Whv = (const ulonglong2*)(s_gWh + k * 1024);
        const ulonglong2* Wzv = (const ulonglong2*)(s_gWz + k * 1024);
        #pragma unroll
        for (int kk = 0; kk < DIMX; kk++) {
            u64 gvA = pack2(ghA[kk]);
            u64 gvB = pack2(ghB[kk]);
            u64 hvA = pack2(hA[kk]);
            u64 hvB = pack2(hB[kk]);
            #pragma unroll
            for (int q = 0; q < 8; q++) {
                ulonglong2 wh = Whv[kk * 8 + q];
                ulonglong2 wz = Wzv[kk * 8 + q];
                accA[2 * q]     = ffma2(gvA, wh.x, accA[2 * q]);
                accA[2 * q + 1] = ffma2(gvA, wh.y, accA[2 * q + 1]);
                accA[2 * q]     = ffma2(hvA, wz.x, accA[2 * q]);
                accA[2 * q + 1] = ffma2(hvA, wz.y, accA[2 * q + 1]);
                accB[2 * q]     = ffma2(gvB, wh.x, accB[2 * q]);
                accB[2 * q + 1] = ffma2(gvB, wh.y, accB[2 * q + 1]);
                accB[2 * q]     = ffma2(hvB, wz.x, accB[2 * q]);
                accB[2 * q + 1] = ffma2(hvB, wz.y, accB[2 * q + 1]);
            }
        }
        #pragma unroll
        for (int q = 0; q < 16; q++) {
            float2 vA = unpack2(accA[q]);
            float2 vB = unpack2(accB[q]);
            ghA[2 * q]     = __sinf(vA.x);
            ghA[2 * q + 1] = __sinf(vA.y);
            ghB[2 * q]     = __sinf(vB.x);
            ghB[2 * q + 1] = __sinf(vB.y);
        }
    }

    // ---- decode ----
    float u0 = dB[0], u1 = dB[0];
    #pragma unroll
    for (int d = 0; d < DIMX; d++) {
        float w = s_dW[d];
        u0 = fmaf(ghA[d], w, u0);
        u1 = fmaf(ghB[d], w, u1);
    }
    const int row = (b * NN + i) * NN;
    out[row + j0] = u0;
    out[row + j1] = u1;
}

extern "C" void kernel_launch(void* const* d_in, const int* in_sizes, int n_in,
                              void* d_out, int out_size) {
    const float* coords   = (const float*)d_in[0];
    const float* x_params = (const float*)d_in[1];
    const float* t_params = (const float*)d_in[2];
    const float* xW1 = (const float*)d_in[3];
    const float* xb1 = (const float*)d_in[4];
    const float* xW2 = (const float*)d_in[5];
    const float* xb2 = (const float*)d_in[6];
    const float* tW1 = (const float*)d_in[7];
    const float* tb1 = (const float*)d_in[8];
    const float* tW2 = (const float*)d_in[9];
    const float* tb2 = (const float*)d_in[10];
    const float* h0  = (const float*)d_in[11];
    const float* gh0 = (const float*)d_in[12];
    const float* f_Wh = (const float*)d_in[13];
    const float* f_bh = (const float*)d_in[14];
    const float* f_Wz = (const float*)d_in[15];
    const float* f_bz = (const float*)d_in[16];
    const float* g_Wh = (const float*)d_in[17];
    const float* g_bh = (const float*)d_in[18];
    const float* g_Wz = (const float*)d_in[19];
    const float* g_bz = (const float*)d_in[20];
    const float* dW   = (const float*)d_in[21];
    const float* dB   = (const float*)d_in[22];

    precompute_kernel<<<BB, 32>>>(x_params, t_params, xW1, xb1, xW2, xb2,
                                  tW1, tb1, tW2, tb2,
                                  f_bh, f_Wz, f_bz, g_bh, g_Wz, g_bz);

    cudaFuncSetAttribute(pde_kernel, cudaFuncAttributeMaxDynamicSharedMemorySize, SMEM_BYTES);

    const int blocks = BB * 128;   // 2048: 2 rows per block, 2 pairs per thread
    pde_kernel<<<blocks, 256, SMEM_BYTES>>>(coords, f_Wh, f_Wz, g_Wh, g_Wz,
                                            h0, gh0, dW, dB, (float*)d_out);
}

// round 4
// speedup vs baseline: 1.3954x; 1.0151x over previous
#include <cuda_runtime.h>
#include <cstdint>

#define DIMX 32
#define NB   6
#define BB   16
#define NN   256
#define XPD  16
#define TPD  8

typedef unsigned long long u64;

// Per-batch folded constants (layer-0 matvecs folded in):
__device__ float g_cf[BB * NB * DIMX];
__device__ float g_cg[BB * NB * DIMX];

// ---------------- packed f32x2 helpers ----------------
__device__ __forceinline__ u64 ffma2(u64 a, u64 b, u64 c) {
    u64 d;
    asm("fma.rn.f32x2 %0, %1, %2, %3;" : "=l"(d) : "l"(a), "l"(b), "l"(c));
    return d;
}
__device__ __forceinline__ u64 pack2(float v) {
    u64 r;
    asm("mov.b64 %0, {%1, %1};" : "=l"(r) : "f"(v));
    return r;
}
__device__ __forceinline__ float2 unpack2(u64 v) {
    float lo, hi;
    asm("mov.b64 {%0, %1}, %2;" : "=f"(lo), "=f"(hi) : "l"(v));
    return make_float2(lo, hi);
}

// ---------------- precompute: embeddings + folded constants ----------------
__global__ void precompute_kernel(
    const float* __restrict__ x_params, const float* __restrict__ t_params,
    const float* __restrict__ xW1, const float* __restrict__ xb1,
    const float* __restrict__ xW2, const float* __restrict__ xb2,
    const float* __restrict__ tW1, const float* __restrict__ tb1,
    const float* __restrict__ tW2, const float* __restrict__ tb2,
    const float* __restrict__ f_bh, const float* __restrict__ f_Wz, const float* __restrict__ f_bz,
    const float* __restrict__ g_bh, const float* __restrict__ g_Wz, const float* __restrict__ g_bz,
    const float* __restrict__ h0,   const float* __restrict__ gh0,
    const float* __restrict__ f_Wh, const float* __restrict__ g_Wh)
{
    int b = blockIdx.x;
    int d = threadIdx.x;  // 0..31
    __shared__ float hid[DIMX], ex_s[DIMX], et_s[DIMX];

    float a = xb1[d];
    #pragma unroll
    for (int m = 0; m < XPD; m++) a += x_params[b * XPD + m] * xW1[m * DIMX + d];
    hid[d] = sinf(a);
    __syncthreads();
    float e = xb2[d];
    #pragma unroll
    for (int m = 0; m < DIMX; m++) e += hid[m] * xW2[m * DIMX + d];
    ex_s[d] = e;
    __syncthreads();

    a = tb1[d];
    #pragma unroll
    for (int m = 0; m < TPD; m++) a += t_params[b * TPD + m] * tW1[m * DIMX + d];
    hid[d] = sinf(a);
    __syncthreads();
    e = tb2[d];
    #pragma unroll
    for (int m = 0; m < DIMX; m++) e += hid[m] * tW2[m * DIMX + d];
    et_s[d] = e;
    __syncthreads();

    for (int k = 0; k < NB; k++) {
        float cf = f_bh[k * DIMX + d] + f_bz[k * DIMX + d];
        const float* Wz = f_Wz + k * 34 * DIMX;
        #pragma unroll
        for (int m = 0; m < DIMX; m++) cf += et_s[m] * Wz[(2 + m) * DIMX + d];
        if (k == 0) {   // fold h0 @ f_Wh[0]
            #pragma unroll
            for (int m = 0; m < DIMX; m++) cf += h0[m] * f_Wh[m * DIMX + d];
        }
        g_cf[(b * NB + k) * DIMX + d] = cf;

        float cg = g_bh[k * DIMX + d] + g_bz[k * DIMX + d];
        const float* gWz = g_Wz + k * 64 * DIMX;
        #pragma unroll
        for (int m = 0; m < DIMX; m++) cg += ex_s[m] * gWz[(32 + m) * DIMX + d];
        if (k == 0) {   // fold gh0 @ g_Wh[0]
            #pragma unroll
            for (int m = 0; m < DIMX; m++) cg += gh0[m] * g_Wh[m * DIMX + d];
        }
        g_cg[(b * NB + k) * DIMX + d] = cg;
    }
}

// ---------------- main kernel ----------------
// smem float offsets:
#define OFF_FWH 0        // f_Wh[1..5]   5*1024
#define OFF_GWH 5120     // g_Wh[1..5]   5*1024
#define OFF_GWZ 10240    // g_Wz[0..5] rows 0..31   6*1024
#define OFF_WZX 16384    // 6*32
#define OFF_WZT 16576
#define OFF_CF  16768
#define OFF_CG  16960
#define OFF_DW  17152    // 32
#define OFF_DB  17184
#define OFF_H   17216    // h state:  2*32*256 floats
#define OFF_GH  33600    // gh state: 2*32*256 floats
#define SMEM_FLOATS 49984
#define SMEM_BYTES  (SMEM_FLOATS * 4)   // 199936 B

extern __shared__ float smem[];

__global__ void __launch_bounds__(256, 1) pde_kernel(
    const float* __restrict__ coords,
    const float* __restrict__ f_Wh,
    const float* __restrict__ f_Wz,
    const float* __restrict__ g_Wh,
    const float* __restrict__ g_Wz,
    const float* __restrict__ dW,
    const float* __restrict__ dB,
    float* __restrict__ out)
{
    const int tid = threadIdx.x;
    const int b  = blockIdx.x >> 7;
    const int i  = ((blockIdx.x & 127) << 1) + (tid >> 7);
    const int j0 = tid & 127;
    const int j1 = j0 + 128;

    // ---- cooperative staging ----
    for (int q = tid; q < 1280; q += 256) {              // f_Wh[1..5]
        int k = q >> 8, r = q & 255;
        ((float4*)(smem + OFF_FWH))[q] = ((const float4*)(f_Wh + (k + 1) * 1024))[r];
    }
    for (int q = tid; q < 1280; q += 256) {              // g_Wh[1..5]
        int k = q >> 8, r = q & 255;
        ((float4*)(smem + OFF_GWH))[q] = ((const float4*)(g_Wh + (k + 1) * 1024))[r];
    }
    for (int q = tid; q < 1536; q += 256) {              // g_Wz[0..5] rows 0..31
        int k = q >> 8, r = q & 255;
        ((float4*)(smem + OFF_GWZ))[q] = ((const float4*)(g_Wz + k * 2048))[r];
    }
    if (tid < 192) {
        int k = tid >> 5, d = tid & 31;
        smem[OFF_WZX + tid] = f_Wz[k * 34 * DIMX + d];
        smem[OFF_WZT + tid] = f_Wz[k * 34 * DIMX + DIMX + d];
        smem[OFF_CF  + tid] = g_cf[b * (NB * DIMX) + tid];
        smem[OFF_CG  + tid] = g_cg[b * (NB * DIMX) + tid];
    }
    if (tid < 32) smem[OFF_DW + tid] = dW[tid];
    if (tid == 0) smem[OFF_DB] = dB[0];
    __syncthreads();

    const float x0 = coords[(b * NN + j0) * 2 + 0];
    const float x1 = coords[(b * NN + j1) * 2 + 0];
    const float t  = coords[(b * NN + i) * 2 + 1];
    const u64 xx0 = pack2(x0);
    const u64 xx1 = pack2(x1);
    const u64 tt  = pack2(t);

    // private smem state columns (conflict-free, no cross-thread sharing)
    float* hA_s = smem + OFF_H  + tid;
    float* hB_s = smem + OFF_H  + 8192 + tid;
    float* gA_s = smem + OFF_GH + tid;
    float* gB_s = smem + OFF_GH + 8192 + tid;

    // ---- f layer 0 (GEMM folded into cf0) ----
    {
        const float4* wx4 = (const float4*)(smem + OFF_WZX);
        const float4* wt4 = (const float4*)(smem + OFF_WZT);
        const float4* cf4 = (const float4*)(smem + OFF_CF);
        #pragma unroll
        for (int q = 0; q < 8; q++) {
            float4 a = wx4[q], bq = wt4[q], c = cf4[q];
            float b0 = fmaf(t, bq.x, c.x), b1 = fmaf(t, bq.y, c.y);
            float b2 = fmaf(t, bq.z, c.z), b3 = fmaf(t, bq.w, c.w);
            hA_s[(4*q+0)*256] = __sinf(fmaf(x0, a.x, b0));
            hA_s[(4*q+1)*256] = __sinf(fmaf(x0, a.y, b1));
            hA_s[(4*q+2)*256] = __sinf(fmaf(x0, a.z, b2));
            hA_s[(4*q+3)*256] = __sinf(fmaf(x0, a.w, b3));
            hB_s[(4*q+0)*256] = __sinf(fmaf(x1, a.x, b0));
            hB_s[(4*q+1)*256] = __sinf(fmaf(x1, a.y, b1));
            hB_s[(4*q+2)*256] = __sinf(fmaf(x1, a.z, b2));
            hB_s[(4*q+3)*256] = __sinf(fmaf(x1, a.w, b3));
        }
    }

    // ---- f layers 1..5 ----
    #pragma unroll 1
    for (int k = 1; k < 6; k++) {
        u64 accA[16], accB[16];
        {
            const ulonglong2* c4 = (const ulonglong2*)(smem + OFF_CF  + k * 32);
            const ulonglong2* wx = (const ulonglong2*)(smem + OFF_WZX + k * 32);
            const ulonglong2* wt = (const ulonglong2*)(smem + OFF_WZT + k * 32);
            #pragma unroll
            for (int q = 0; q < 8; q++) {
                ulonglong2 c = c4[q], a = wx[q], bq = wt[q];
                u64 b0 = ffma2(tt, bq.x, c.x);
                u64 b1 = ffma2(tt, bq.y, c.y);
                accA[2*q]   = ffma2(xx0, a.x, b0);
                accA[2*q+1] = ffma2(xx0, a.y, b1);
                accB[2*q]   = ffma2(xx1, a.x, b0);
                accB[2*q+1] = ffma2(xx1, a.y, b1);
            }
        }
        const ulonglong2* W = (const ulonglong2*)(smem + OFF_FWH + (k - 1) * 1024);
        #pragma unroll 4
        for (int kk = 0; kk < 32; kk++) {
            u64 hA = pack2(hA_s[kk * 256]);
            u64 hB = pack2(hB_s[kk * 256]);
            #pragma unroll
            for (int q = 0; q < 8; q++) {
                ulonglong2 w = W[kk * 8 + q];
                accA[2*q]   = ffma2(hA, w.x, accA[2*q]);
                accA[2*q+1] = ffma2(hA, w.y, accA[2*q+1]);
                accB[2*q]   = ffma2(hB, w.x, accB[2*q]);
                accB[2*q+1] = ffma2(hB, w.y, accB[2*q+1]);
            }
        }
        #pragma unroll
        for (int q = 0; q < 16; q++) {
            float2 a = unpack2(accA[q]);
            float2 c = unpack2(accB[q]);
            hA_s[(2*q)*256]   = __sinf(a.x);
            hA_s[(2*q+1)*256] = __sinf(a.y);
            hB_s[(2*q)*256]   = __sinf(c.x);
            hB_s[(2*q+1)*256] = __sinf(c.y);
        }
    }

    // ---- g layer 0: gh1 = sin(h @ gWz0 + cg0)  (gh0@gWh0 folded) ----
    {
        u64 accA[16], accB[16];
        const ulonglong2* c4 = (const ulonglong2*)(smem + OFF_CG);
        #pragma unroll
        for (int q = 0; q < 8; q++) {
            ulonglong2 c = c4[q];
            accA[2*q] = c.x; accA[2*q+1] = c.y;
            accB[2*q] = c.x; accB[2*q+1] = c.y;
        }
        const ulonglong2* W = (const ulonglong2*)(smem + OFF_GWZ);
        #pragma unroll 4
        for (int kk = 0; kk < 32; kk++) {
            u64 hA = pack2(hA_s[kk * 256]);
            u64 hB = pack2(hB_s[kk * 256]);
            #pragma unroll
            for (int q = 0; q < 8; q++) {
                ulonglong2 w = W[kk * 8 + q];
                accA[2*q]   = ffma2(hA, w.x, accA[2*q]);
                accA[2*q+1] = ffma2(hA, w.y, accA[2*q+1]);
                accB[2*q]   = ffma2(hB, w.x, accB[2*q]);
                accB[2*q+1] = ffma2(hB, w.y, accB[2*q+1]);
            }
        }
        #pragma unroll
        for (int q = 0; q < 16; q++) {
            float2 a = unpack2(accA[q]);
            float2 c = unpack2(accB[q]);
            gA_s[(2*q)*256]   = __sinf(a.x);
            gA_s[(2*q+1)*256] = __sinf(a.y);
            gB_s[(2*q)*256]   = __sinf(c.x);
            gB_s[(2*q+1)*256] = __sinf(c.y);
        }
    }

    // ---- g layers 1..5 (dual matvec), decode folded into k==5 ----
    float uA = smem[OFF_DB], uB = uA;
    #pragma unroll 1
    for (int k = 1; k < 6; k++) {
        u64 accA[16], accB[16];
        {
            const ulonglong2* c4 = (const ulonglong2*)(smem + OFF_CG + k * 32);
            #pragma unroll
            for (int q = 0; q < 8; q++) {
                ulonglong2 c = c4[q];
                accA[2*q] = c.x; accA[2*q+1] = c.y;
                accB[2*q] = c.x; accB[2*q+1] = c.y;
            }
        }
        const ulonglong2* Wh = (const ulonglong2*)(smem + OFF_GWH + (k - 1) * 1024);
        const ulonglong2* Wz = (const ulonglong2*)(smem + OFF_GWZ + k * 1024);
        #pragma unroll 2
        for (int kk = 0; kk < 32; kk++) {
            u64 gA = pack2(gA_s[kk * 256]);
            u64 gB = pack2(gB_s[kk * 256]);
            u64 hA = pack2(hA_s[kk * 256]);
            u64 hB = pack2(hB_s[kk * 256]);
            #pragma unroll
            for (int q = 0; q < 8; q++) {
                ulonglong2 wh = Wh[kk * 8 + q];
                ulonglong2 wz = Wz[kk * 8 + q];
                accA[2*q]   = ffma2(gA, wh.x, accA[2*q]);
                accA[2*q]   = ffma2(hA, wz.x, accA[2*q]);
                accA[2*q+1] = ffma2(gA, wh.y, accA[2*q+1]);
                accA[2*q+1] = ffma2(hA, wz.y, accA[2*q+1]);
                accB[2*q]   = ffma2(gB, wh.x, accB[2*q]);
                accB[2*q]   = ffma2(hB, wz.x, accB[2*q]);
                accB[2*q+1] = ffma2(gB, wh.y, accB[2*q+1]);
                accB[2*q+1] = ffma2(hB, wz.y, accB[2*q+1]);
            }
        }
        if (k < 5) {
            #pragma unroll
            for (int q = 0; q < 16; q++) {
                float2 a = unpack2(accA[q]);
                float2 c = unpack2(accB[q]);
                gA_s[(2*q)*256]   = __sinf(a.x);
                gA_s[(2*q+1)*256] = __sinf(a.y);
                gB_s[(2*q)*256]   = __sinf(c.x);
                gB_s[(2*q+1)*256] = __sinf(c.y);
            }
        } else {
            const float* dw = smem + OFF_DW;
            #pragma unroll
            for (int q = 0; q < 16; q++) {
                float2 a = unpack2(accA[q]);
                float2 c = unpack2(accB[q]);
                float w0 = dw[2*q], w1 = dw[2*q+1];
                uA = fmaf(__sinf(a.x), w0, uA);
                uA = fmaf(__sinf(a.y), w1, uA);
                uB = fmaf(__sinf(c.x), w0, uB);
                uB = fmaf(__sinf(c.y), w1, uB);
            }
        }
    }

    const int row = (b * NN + i) * NN;
    out[row + j0] = uA;
    out[row + j1] = uB;
}

extern "C" void kernel_launch(void* const* d_in, const int* in_sizes, int n_in,
                              void* d_out, int out_size) {
    const float* coords   = (const float*)d_in[0];
    const float* x_params = (const float*)d_in[1];
    const float* t_params = (const float*)d_in[2];
    const float* xW1 = (const float*)d_in[3];
    const float* xb1 = (const float*)d_in[4];
    const float* xW2 = (const float*)d_in[5];
    const float* xb2 = (const float*)d_in[6];
    const float* tW1 = (const float*)d_in[7];
    const float* tb1 = (const float*)d_in[8];
    const float* tW2 = (const float*)d_in[9];
    const float* tb2 = (const float*)d_in[10];
    const float* h0  = (const float*)d_in[11];
    const float* gh0 = (const float*)d_in[12];
    const float* f_Wh = (const float*)d_in[13];
    const float* f_bh = (const float*)d_in[14];
    const float* f_Wz = (const float*)d_in[15];
    const float* f_bz = (const float*)d_in[16];
    const float* g_Wh = (const float*)d_in[17];
    const float* g_bh = (const float*)d_in[18];
    const float* g_Wz = (const float*)d_in[19];
    const float* g_bz = (const float*)d_in[20];
    const float* dW   = (const float*)d_in[21];
    const float* dB   = (const float*)d_in[22];

    precompute_kernel<<<BB, 32>>>(x_params, t_params, xW1, xb1, xW2, xb2,
                                  tW1, tb1, tW2, tb2,
                                  f_bh, f_Wz, f_bz, g_bh, g_Wz, g_bz,
                                  h0, gh0, f_Wh, g_Wh);

    cudaFuncSetAttribute(pde_kernel, cudaFuncAttributeMaxDynamicSharedMemorySize, SMEM_BYTES);

    const int blocks = BB * 128;   // 2048
    pde_kernel<<<blocks, 256, SMEM_BYTES>>>(coords, f_Wh, f_Wz, g_Wh, g_Wz,
                                            dW, dB, (float*)d_out);
}

// round 7
// speedup vs baseline: 1.3994x; 1.0029x over previous
#include <cuda_runtime.h>
#include <cstdint>

#define DIMX 32
#define NB   6
#define BB   16
#define NN   256
#define XPD  16
#define TPD  8

typedef unsigned long long u64;

// Per-batch folded constants (layer-0 matvecs folded in):
__device__ __align__(16) float g_cf[BB * NB * DIMX];
__device__ __align__(16) float g_cg[BB * NB * DIMX];

// ---------------- packed f32x2 helpers ----------------
__device__ __forceinline__ u64 ffma2(u64 a, u64 b, u64 c) {
    u64 d;
    asm("fma.rn.f32x2 %0, %1, %2, %3;" : "=l"(d) : "l"(a), "l"(b), "l"(c));
    return d;
}
__device__ __forceinline__ u64 pack2(float v) {
    u64 r;
    asm("mov.b64 %0, {%1, %1};" : "=l"(r) : "f"(v));
    return r;
}
__device__ __forceinline__ float2 unpack2(u64 v) {
    float lo, hi;
    asm("mov.b64 {%0, %1}, %2;" : "=f"(lo), "=f"(hi) : "l"(v));
    return make_float2(lo, hi);
}

// ---------------- precompute: embeddings + folded constants ----------------
__global__ void precompute_kernel(
    const float* __restrict__ x_params, const float* __restrict__ t_params,
    const float* __restrict__ xW1, const float* __restrict__ xb1,
    const float* __restrict__ xW2, const float* __restrict__ xb2,
    const float* __restrict__ tW1, const float* __restrict__ tb1,
    const float* __restrict__ tW2, const float* __restrict__ tb2,
    const float* __restrict__ f_bh, const float* __restrict__ f_Wz, const float* __restrict__ f_bz,
    const float* __restrict__ g_bh, const float* __restrict__ g_Wz, const float* __restrict__ g_bz,
    const float* __restrict__ h0,   const float* __restrict__ gh0,
    const float* __restrict__ f_Wh, const float* __restrict__ g_Wh)
{
    int b = blockIdx.x;
    int d = threadIdx.x;  // 0..31
    __shared__ float hid[DIMX], ex_s[DIMX], et_s[DIMX];

    float a = xb1[d];
    #pragma unroll
    for (int m = 0; m < XPD; m++) a += x_params[b * XPD + m] * xW1[m * DIMX + d];
    hid[d] = sinf(a);
    __syncthreads();
    float e = xb2[d];
    #pragma unroll
    for (int m = 0; m < DIMX; m++) e += hid[m] * xW2[m * DIMX + d];
    ex_s[d] = e;
    __syncthreads();

    a = tb1[d];
    #pragma unroll
    for (int m = 0; m < TPD; m++) a += t_params[b * TPD + m] * tW1[m * DIMX + d];
    hid[d] = sinf(a);
    __syncthreads();
    e = tb2[d];
    #pragma unroll
    for (int m = 0; m < DIMX; m++) e += hid[m] * tW2[m * DIMX + d];
    et_s[d] = e;
    __syncthreads();

    for (int k = 0; k < NB; k++) {
        float cf = f_bh[k * DIMX + d] + f_bz[k * DIMX + d];
        const float* Wz = f_Wz + k * 34 * DIMX;
        #pragma unroll
        for (int m = 0; m < DIMX; m++) cf += et_s[m] * Wz[(2 + m) * DIMX + d];
        if (k == 0) {
            #pragma unroll
            for (int m = 0; m < DIMX; m++) cf += h0[m] * f_Wh[m * DIMX + d];
        }
        g_cf[(b * NB + k) * DIMX + d] = cf;

        float cg = g_bh[k * DIMX + d] + g_bz[k * DIMX + d];
        const float* gWz = g_Wz + k * 64 * DIMX;
        #pragma unroll
        for (int m = 0; m < DIMX; m++) cg += ex_s[m] * gWz[(32 + m) * DIMX + d];
        if (k == 0) {
            #pragma unroll
            for (int m = 0; m < DIMX; m++) cg += gh0[m] * g_Wh[m * DIMX + d];
        }
        g_cg[(b * NB + k) * DIMX + d] = cg;
    }
}

// ---------------- main kernel ----------------
// smem float offsets:
#define OFF_FWH 0        // f_Wh[1..5]   5*1024
#define OFF_GWH 5120     // g_Wh[1..5]   5*1024
#define OFF_GWZ 10240    // g_Wz[0..5] rows 0..31   6*1024
#define OFF_WZX 16384    // 6*32
#define OFF_WZT 16576
#define OFF_DW  16768    // 32
#define OFF_DB  16800    // 1 (+pad)
#define OFF_H   16832    // final-h state: 2 * 32 * 384 floats
#define SMEM_FLOATS 41408
#define SMEM_BYTES  (SMEM_FLOATS * 4)   // 165632 B -> 1 CTA/SM, 12 warps

#define TPB 384
#define NROWS_TOTAL (BB * NN)           // 4096
#define GRID ((NROWS_TOTAL + 2) / 3)    // 1366

extern __shared__ float smem[];

__global__ void __launch_bounds__(TPB, 1) pde_kernel(
    const float* __restrict__ coords,
    const float* __restrict__ f_Wh,
    const float* __restrict__ g_Wh,
    const float* __restrict__ g_Wz,
    const float* __restrict__ f_Wz,
    const float* __restrict__ dW,
    const float* __restrict__ dB,
    float* __restrict__ out)
{
    const int tid = threadIdx.x;

    // ---- cooperative staging (batch-independent weights only) ----
    for (int q = tid; q < 1280; q += TPB) {              // f_Wh[1..5]
        int k = q >> 8, r = q & 255;
        ((float4*)(smem + OFF_FWH))[q] = ((const float4*)(f_Wh + (k + 1) * 1024))[r];
    }
    for (int q = tid; q < 1280; q += TPB) {              // g_Wh[1..5]
        int k = q >> 8, r = q & 255;
        ((float4*)(smem + OFF_GWH))[q] = ((const float4*)(g_Wh + (k + 1) * 1024))[r];
    }
    for (int q = tid; q < 1536; q += TPB) {              // g_Wz[0..5] rows 0..31
        int k = q >> 8, r = q & 255;
        ((float4*)(smem + OFF_GWZ))[q] = ((const float4*)(g_Wz + k * 2048))[r];
    }
    if (tid < 192) {
        int k = tid >> 5, d = tid & 31;
        smem[OFF_WZX + tid] = f_Wz[k * 34 * DIMX + d];
        smem[OFF_WZT + tid] = f_Wz[k * 34 * DIMX + DIMX + d];
    }
    if (tid < 32) smem[OFF_DW + tid] = dW[tid];
    if (tid == 0) smem[OFF_DB] = dB[0];
    __syncthreads();

    const int row = blockIdx.x * 3 + (tid >> 7);   // global (b,i) row
    if (row >= NROWS_TOTAL) return;                // no barriers after this point
    const int b  = row >> 8;
    const int i  = row & 255;
    const int j0 = tid & 127;
    const int j1 = j0 + 128;

    const float x0 = coords[(b * NN + j0) * 2 + 0];
    const float x1 = coords[(b * NN + j1) * 2 + 0];
    const float t  = coords[(b * NN + i) * 2 + 1];
    const u64 xx0 = pack2(x0);
    const u64 xx1 = pack2(x1);
    const u64 tt  = pack2(t);

    const float* cfb = g_cf + b * (NB * DIMX);
    const float* cgb = g_cg + b * (NB * DIMX);

    float hA[DIMX], hB[DIMX];

    // ---- f layer 0 (h0@Wh0 folded into cf0) ----
    {
        const float4* wx4 = (const float4*)(smem + OFF_WZX);
        const float4* wt4 = (const float4*)(smem + OFF_WZT);
        const float4* cf4 = (const float4*)(cfb);
        #pragma unroll
        for (int q = 0; q < 8; q++) {
            float4 a = wx4[q], bq = wt4[q], c = cf4[q];
            float b0 = fmaf(t, bq.x, c.x), b1 = fmaf(t, bq.y, c.y);
            float b2 = fmaf(t, bq.z, c.z), b3 = fmaf(t, bq.w, c.w);
            hA[4*q+0] = __sinf(fmaf(x0, a.x, b0));
            hA[4*q+1] = __sinf(fmaf(x0, a.y, b1));
            hA[4*q+2] = __sinf(fmaf(x0, a.z, b2));
            hA[4*q+3] = __sinf(fmaf(x0, a.w, b3));
            hB[4*q+0] = __sinf(fmaf(x1, a.x, b0));
            hB[4*q+1] = __sinf(fmaf(x1, a.y, b1));
            hB[4*q+2] = __sinf(fmaf(x1, a.z, b2));
            hB[4*q+3] = __sinf(fmaf(x1, a.w, b3));
        }
    }

    // ---- f layers 1..5 (h in registers; kk fully unrolled) ----
    #pragma unroll 1
    for (int k = 1; k < 6; k++) {
        u64 accA[16], accB[16];
        {
            const ulonglong2* c4 = (const ulonglong2*)(cfb + k * 32);
            const ulonglong2* wx = (const ulonglong2*)(smem + OFF_WZX + k * 32);
            const ulonglong2* wt = (const ulonglong2*)(smem + OFF_WZT + k * 32);
            #pragma unroll
            for (int q = 0; q < 8; q++) {
                ulonglong2 c = c4[q], a = wx[q], bq = wt[q];
                u64 b0 = ffma2(tt, bq.x, c.x);
                u64 b1 = ffma2(tt, bq.y, c.y);
                accA[2*q]   = ffma2(xx0, a.x, b0);
                accA[2*q+1] = ffma2(xx0, a.y, b1);
                accB[2*q]   = ffma2(xx1, a.x, b0);
                accB[2*q+1] = ffma2(xx1, a.y, b1);
            }
        }
        const ulonglong2* W = (const ulonglong2*)(smem + OFF_FWH + (k - 1) * 1024);
        #pragma unroll
        for (int kk = 0; kk < 32; kk++) {
            u64 a2 = pack2(hA[kk]);
            u64 b2 = pack2(hB[kk]);
            #pragma unroll
            for (int q = 0; q < 8; q++) {
                ulonglong2 w = W[kk * 8 + q];
                accA[2*q]   = ffma2(a2, w.x, accA[2*q]);
                accA[2*q+1] = ffma2(a2, w.y, accA[2*q+1]);
                accB[2*q]   = ffma2(b2, w.x, accB[2*q]);
                accB[2*q+1] = ffma2(b2, w.y, accB[2*q+1]);
            }
        }
        #pragma unroll
        for (int q = 0; q < 16; q++) {
            float2 a = unpack2(accA[q]);
            float2 c = unpack2(accB[q]);
            hA[2*q]   = __sinf(a.x);
            hA[2*q+1] = __sinf(a.y);
            hB[2*q]   = __sinf(c.x);
            hB[2*q+1] = __sinf(c.y);
        }
    }

    // ---- persist final h to smem (needed by g layers 1..5) ----
    float* hA_s = smem + OFF_H + tid;
    float* hB_s = smem + OFF_H + 12288 + tid;
    #pragma unroll
    for (int kk = 0; kk < 32; kk++) {
        hA_s[kk * TPB] = hA[kk];
        hB_s[kk * TPB] = hB[kk];
    }

    // ---- g layer 0: gh1 = sin(h @ gWz0 + cg0), h still in regs ----
    float ghA[DIMX], ghB[DIMX];
    {
        u64 accA[16], accB[16];
        const ulonglong2* c4 = (const ulonglong2*)(cgb);
        #pragma unroll
        for (int q = 0; q < 8; q++) {
            ulonglong2 c = c4[q];
            accA[2*q] = c.x; accA[2*q+1] = c.y;
            accB[2*q] = c.x; accB[2*q+1] = c.y;
        }
        const ulonglong2* W = (const ulonglong2*)(smem + OFF_GWZ);
        #pragma unroll
        for (int kk = 0; kk < 32; kk++) {
            u64 a2 = pack2(hA[kk]);
            u64 b2 = pack2(hB[kk]);
            #pragma unroll
            for (int q = 0; q < 8; q++) {
                ulonglong2 w = W[kk * 8 + q];
                accA[2*q]   = ffma2(a2, w.x, accA[2*q]);
                accA[2*q+1] = ffma2(a2, w.y, accA[2*q+1]);
                accB[2*q]   = ffma2(b2, w.x, accB[2*q]);
                accB[2*q+1] = ffma2(b2, w.y, accB[2*q+1]);
            }
        }
        #pragma unroll
        for (int q = 0; q < 16; q++) {
            float2 a = unpack2(accA[q]);
            float2 c = unpack2(accB[q]);
            ghA[2*q]   = __sinf(a.x);
            ghA[2*q+1] = __sinf(a.y);
            ghB[2*q]   = __sinf(c.x);
            ghB[2*q+1] = __sinf(c.y);
        }
    }

    // ---- g layers 1..5: gh in regs, h from smem; decode folded into k==5 ----
    float uA = smem[OFF_DB], uB = uA;
    #pragma unroll 1
    for (int k = 1; k < 6; k++) {
        u64 accA[16], accB[16];
        {
            const ulonglong2* c4 = (const ulonglong2*)(cgb + k * 32);
            #pragma unroll
            for (int q = 0; q < 8; q++) {
                ulonglong2 c = c4[q];
                accA[2*q] = c.x; accA[2*q+1] = c.y;
                accB[2*q] = c.x; accB[2*q+1] = c.y;
            }
        }
        const ulonglong2* Wh = (const ulonglong2*)(smem + OFF_GWH + (k - 1) * 1024);
        const ulonglong2* Wz = (const ulonglong2*)(smem + OFF_GWZ + k * 1024);
        #pragma unroll
        for (int kk = 0; kk < 32; kk++) {
            u64 gA = pack2(ghA[kk]);
            u64 gB = pack2(ghB[kk]);
            u64 a2 = pack2(hA_s[kk * TPB]);
            u64 b2 = pack2(hB_s[kk * TPB]);
            #pragma unroll
            for (int q = 0; q < 8; q++) {
                ulonglong2 wh = Wh[kk * 8 + q];
                ulonglong2 wz = Wz[kk * 8 + q];
                accA[2*q]   = ffma2(gA, wh.x, accA[2*q]);
                accA[2*q]   = ffma2(a2, wz.x, accA[2*q]);
                accA[2*q+1] = ffma2(gA, wh.y, accA[2*q+1]);
                accA[2*q+1] = ffma2(a2, wz.y, accA[2*q+1]);
                accB[2*q]   = ffma2(gB, wh.x, accB[2*q]);
                accB[2*q]   = ffma2(b2, wz.x, accB[2*q]);
                accB[2*q+1] = ffma2(gB, wh.y, accB[2*q+1]);
                accB[2*q+1] = ffma2(b2, wz.y, accB[2*q+1]);
            }
        }
        if (k < 5) {
            #pragma unroll
            for (int q = 0; q < 16; q++) {
                float2 a = unpack2(accA[q]);
                float2 c = unpack2(accB[q]);
                ghA[2*q]   = __sinf(a.x);
                ghA[2*q+1] = __sinf(a.y);
                ghB[2*q]   = __sinf(c.x);
                ghB[2*q+1] = __sinf(c.y);
            }
        } else {
            const float* dw = smem + OFF_DW;
            #pragma unroll
            for (int q = 0; q < 16; q++) {
                float2 a = unpack2(accA[q]);
                float2 c = unpack2(accB[q]);
                float w0 = dw[2*q], w1 = dw[2*q+1];
                uA = fmaf(__sinf(a.x), w0, uA);
                uA = fmaf(__sinf(a.y), w1, uA);
                uB = fmaf(__sinf(c.x), w0, uB);
                uB = fmaf(__sinf(c.y), w1, uB);
            }
        }
    }

    const int rowbase = row * NN;
    out[rowbase + j0] = uA;
    out[rowbase + j1] = uB;
}

extern "C" void kernel_launch(void* const* d_in, const int* in_sizes, int n_in,
                              void* d_out, int out_size) {
    const float* coords   = (const float*)d_in[0];
    const float* x_params = (const float*)d_in[1];
    const float* t_params = (const float*)d_in[2];
    const float* xW1 = (const float*)d_in[3];
    const float* xb1 = (const float*)d_in[4];
    const float* xW2 = (const float*)d_in[5];
    const float* xb2 = (const float*)d_in[6];
    const float* tW1 = (const float*)d_in[7];
    const float* tb1 = (const float*)d_in[8];
    const float* tW2 = (const float*)d_in[9];
    const float* tb2 = (const float*)d_in[10];
    const float* h0  = (const float*)d_in[11];
    const float* gh0 = (const float*)d_in[12];
    const float* f_Wh = (const float*)d_in[13];
    const float* f_bh = (const float*)d_in[14];
    const float* f_Wz = (const float*)d_in[15];
    const float* f_bz = (const float*)d_in[16];
    const float* g_Wh = (const float*)d_in[17];
    const float* g_bh = (const float*)d_in[18];
    const float* g_Wz = (const float*)d_in[19];
    const float* g_bz = (const float*)d_in[20];
    const float* dW   = (const float*)d_in[21];
    const float* dB   = (const float*)d_in[22];

    precompute_kernel<<<BB, 32>>>(x_params, t_params, xW1, xb1, xW2, xb2,
                                  tW1, tb1, tW2, tb2,
                                  f_bh, f_Wz, f_bz, g_bh, g_Wz, g_bz,
                                  h0, gh0, f_Wh, g_Wh);

    cudaFuncSetAttribute(pde_kernel, cudaFuncAttributeMaxDynamicSharedMemorySize, SMEM_BYTES);

    pde_kernel<<<GRID, TPB, SMEM_BYTES>>>(coords, f_Wh, g_Wh, g_Wz, f_Wz,
                                          dW, dB, (float*)d_out);
}